// round 1
// baseline (speedup 1.0000x reference)
#include <cuda_runtime.h>
#include <stdint.h>

#define B 1024
#define D 768

// ---------------- scratch (device globals; no allocation allowed) ----------
__device__ float              g_logits[B * B];   // 4 MB
__device__ unsigned long long g_hash[B];
__device__ int                g_labels[B];
__device__ float              g_loss[B];

// ---------------- hashing --------------------------------------------------
__device__ __forceinline__ unsigned long long splitmix64(unsigned long long x) {
    x += 0x9E3779B97F4A7C15ULL;
    x = (x ^ (x >> 30)) * 0xBF58476D1CE4E5B9ULL;
    x = (x ^ (x >> 27)) * 0x94D049BB133111EBULL;
    return x ^ (x >> 31);
}

// Per-row commutative hash: sum over k of splitmix64((k<<32) ^ bits(row[k])).
// Exact function of the row bits -> equal rows always hash equal.
__global__ void hash_kernel(const float* __restrict__ img) {
    const int j   = blockIdx.x;
    const int tid = threadIdx.x;
    const float* row = img + (size_t)j * D;

    unsigned long long h = 0ULL;
    for (int k = tid; k < D; k += blockDim.x) {
        unsigned int bits = __float_as_uint(row[k]);
        h += splitmix64(((unsigned long long)k << 32) ^ (unsigned long long)bits);
    }
    __shared__ unsigned long long sh[256];
    sh[tid] = h;
    __syncthreads();
    for (int s = 128; s > 0; s >>= 1) {
        if (tid < s) sh[tid] += sh[tid + s];
        __syncthreads();
    }
    if (tid == 0) g_hash[j] = sh[0];
}

// labels[j] = min i (i<=j) with row_i == row_j elementwise.
__global__ void label_kernel(const float* __restrict__ img) {
    const int j   = blockIdx.x;
    const int tid = threadIdx.x;
    __shared__ int s_min;
    if (tid == 0) s_min = j;
    __syncthreads();

    const unsigned long long hj = g_hash[j];
    const float* rj = img + (size_t)j * D;
    for (int i = tid; i < j; i += blockDim.x) {
        if (g_hash[i] == hj) {
            // verify exact elementwise equality (float ==, matches reference)
            const float* ri = img + (size_t)i * D;
            bool eq = true;
            for (int k = 0; k < D; k += 4) {
                float4 a = *reinterpret_cast<const float4*>(ri + k);
                float4 b = *reinterpret_cast<const float4*>(rj + k);
                if (a.x != b.x || a.y != b.y || a.z != b.z || a.w != b.w) { eq = false; break; }
            }
            if (eq) atomicMin(&s_min, i);
        }
    }
    __syncthreads();
    if (tid == 0) g_labels[j] = s_min;
}

// ---------------- GEMM: logits = scale * img @ txt^T -----------------------
// A [B, D] row-major, Bt [B, D] row-major (both K-contiguous) -> NT GEMM.
// 64x64 tile, BK=16, 256 threads, 4x4 micro-tile per thread.
#define BM 64
#define BN 64
#define BK 16

__global__ __launch_bounds__(256)
void gemm_kernel(const float* __restrict__ A, const float* __restrict__ Bt,
                 const float* __restrict__ scale_p) {
    __shared__ float As[BK][BM];
    __shared__ float Bs[BK][BN];

    const int tid = threadIdx.x;
    const int tx = tid & 15;          // 0..15 -> n micro
    const int ty = tid >> 4;          // 0..15 -> m micro
    const int mBase = blockIdx.y * BM;
    const int nBase = blockIdx.x * BN;

    // loader mapping: 256 threads load 64 rows x 16 cols (float4 each)
    const int lrow  = tid >> 2;        // 0..63
    const int lcol4 = (tid & 3) * 4;   // 0,4,8,12

    float acc[4][4];
    #pragma unroll
    for (int i = 0; i < 4; i++)
        #pragma unroll
        for (int n = 0; n < 4; n++) acc[i][n] = 0.0f;

    for (int kt = 0; kt < D; kt += BK) {
        float4 av = *reinterpret_cast<const float4*>(A  + (size_t)(mBase + lrow) * D + kt + lcol4);
        float4 bv = *reinterpret_cast<const float4*>(Bt + (size_t)(nBase + lrow) * D + kt + lcol4);
        As[lcol4 + 0][lrow] = av.x;
        As[lcol4 + 1][lrow] = av.y;
        As[lcol4 + 2][lrow] = av.z;
        As[lcol4 + 3][lrow] = av.w;
        Bs[lcol4 + 0][lrow] = bv.x;
        Bs[lcol4 + 1][lrow] = bv.y;
        Bs[lcol4 + 2][lrow] = bv.z;
        Bs[lcol4 + 3][lrow] = bv.w;
        __syncthreads();

        #pragma unroll
        for (int k = 0; k < BK; k++) {
            float4 a = *reinterpret_cast<const float4*>(&As[k][ty * 4]);
            float4 b = *reinterpret_cast<const float4*>(&Bs[k][tx * 4]);
            float am[4] = {a.x, a.y, a.z, a.w};
            float bn[4] = {b.x, b.y, b.z, b.w};
            #pragma unroll
            for (int i = 0; i < 4; i++)
                #pragma unroll
                for (int n = 0; n < 4; n++)
                    acc[i][n] = fmaf(am[i], bn[n], acc[i][n]);
        }
        __syncthreads();
    }

    const float s = *scale_p;
    #pragma unroll
    for (int i = 0; i < 4; i++) {
        const int m = mBase + ty * 4 + i;
        #pragma unroll
        for (int n = 0; n < 4; n++) {
            g_logits[(size_t)m * B + nBase + tx * 4 + n] = acc[i][n] * s;
        }
    }
}

// ---------------- per-row log-softmax loss ----------------------------------
// loss[j] = logsumexp(logits[j,:]) - logits[j, labels[j]]
__global__ void lse_kernel() {
    const int j   = blockIdx.x;
    const int tid = threadIdx.x;   // 256 threads, 4 elems each
    const float* row = g_logits + (size_t)j * B;

    float4 v = *reinterpret_cast<const float4*>(row + tid * 4);
    float lmax = fmaxf(fmaxf(v.x, v.y), fmaxf(v.z, v.w));

    __shared__ float sh[256];
    sh[tid] = lmax;
    __syncthreads();
    for (int s = 128; s > 0; s >>= 1) {
        if (tid < s) sh[tid] = fmaxf(sh[tid], sh[tid + s]);
        __syncthreads();
    }
    const float gmax = sh[0];
    __syncthreads();

    float lsum = expf(v.x - gmax) + expf(v.y - gmax) + expf(v.z - gmax) + expf(v.w - gmax);
    sh[tid] = lsum;
    __syncthreads();
    for (int s = 128; s > 0; s >>= 1) {
        if (tid < s) sh[tid] += sh[tid + s];
        __syncthreads();
    }
    if (tid == 0) {
        float lse = gmax + logf(sh[0]);
        g_loss[j] = lse - row[g_labels[j]];
    }
}

// ---------------- final deterministic mean ----------------------------------
__global__ void reduce_kernel(float* __restrict__ out) {
    const int tid = threadIdx.x;  // 256 threads
    float s = 0.0f;
    #pragma unroll
    for (int r = 0; r < 4; r++) s += g_loss[tid + r * 256];
    __shared__ float sh[256];
    sh[tid] = s;
    __syncthreads();
    for (int w = 128; w > 0; w >>= 1) {
        if (tid < w) sh[tid] += sh[tid + w];
        __syncthreads();
    }
    if (tid == 0) out[0] = sh[0] * (1.0f / (float)B);
}

// ---------------- entry -----------------------------------------------------
extern "C" void kernel_launch(void* const* d_in, const int* in_sizes, int n_in,
                              void* d_out, int out_size) {
    const float* img   = (const float*)d_in[0];
    const float* txt   = (const float*)d_in[1];
    const float* scale = (const float*)d_in[2];
    float* out = (float*)d_out;

    hash_kernel<<<B, 256>>>(img);
    label_kernel<<<B, 256>>>(img);
    dim3 grid(B / BN, B / BM);
    gemm_kernel<<<grid, 256>>>(img, txt, scale);
    lse_kernel<<<B, 256>>>();
    reduce_kernel<<<1, 256>>>(out);
}

// round 3
// speedup vs baseline: 1.9235x; 1.9235x over previous
#include <cuda_runtime.h>
#include <cuda_bf16.h>
#include <stdint.h>

#define B 1024
#define D 768

// ---------------- scratch (device globals; no allocation allowed) ----------
__device__ float              g_logits[B * B];   // 4 MB
__device__ __nv_bfloat16      g_img_bf[B * D];
__device__ __nv_bfloat16      g_txt_bf[B * D];
__device__ unsigned long long g_hash[B];
__device__ int                g_labels[B];
__device__ float              g_loss[B];

// ---------------- small asm helpers (all base-arch features) ----------------
__device__ __forceinline__ uint32_t smem_to_u32(const void* smem_ptr) {
    uint32_t addr;
    asm("{ .reg .u64 tmp; cvta.to.shared.u64 tmp, %1; cvt.u32.u64 %0, tmp; }"
        : "=r"(addr) : "l"(smem_ptr));
    return addr;
}
#define CP_ASYNC16(smem_u32, gptr) \
    asm volatile("cp.async.cg.shared.global [%0], [%1], 16;" \
                 :: "r"(smem_u32), "l"(gptr) : "memory")
#define CP_COMMIT() asm volatile("cp.async.commit_group;" ::: "memory")
#define CP_WAIT(N)  asm volatile("cp.async.wait_group %0;" :: "n"(N) : "memory")

__device__ __forceinline__ uint32_t lds32(uint32_t addr) {
    uint32_t v;
    asm volatile("ld.shared.b32 %0, [%1];" : "=r"(v) : "r"(addr));
    return v;
}

// mma.sync m16n8k16 row.col bf16 -> f32 accumulate (sm_80 baseline feature)
__device__ __forceinline__ void mma16816(float* d, const uint32_t* a, const uint32_t* b) {
    asm volatile(
        "mma.sync.aligned.m16n8k16.row.col.f32.bf16.bf16.f32 "
        "{%0,%1,%2,%3}, {%4,%5,%6,%7}, {%8,%9}, {%0,%1,%2,%3};"
        : "+f"(d[0]), "+f"(d[1]), "+f"(d[2]), "+f"(d[3])
        : "r"(a[0]), "r"(a[1]), "r"(a[2]), "r"(a[3]), "r"(b[0]), "r"(b[1]));
}

// ---------------- fp32 -> bf16 conversion -----------------------------------
__global__ void convert_kernel(const float* __restrict__ img, const float* __restrict__ txt) {
    const int i = blockIdx.x * blockDim.x + threadIdx.x;   // one float4 each
    float4 a = reinterpret_cast<const float4*>(img)[i];
    float4 b = reinterpret_cast<const float4*>(txt)[i];
    __nv_bfloat162 a01 = __float22bfloat162_rn(make_float2(a.x, a.y));
    __nv_bfloat162 a23 = __float22bfloat162_rn(make_float2(a.z, a.w));
    __nv_bfloat162 b01 = __float22bfloat162_rn(make_float2(b.x, b.y));
    __nv_bfloat162 b23 = __float22bfloat162_rn(make_float2(b.z, b.w));
    uint2 av = make_uint2(*reinterpret_cast<uint32_t*>(&a01), *reinterpret_cast<uint32_t*>(&a23));
    uint2 bv = make_uint2(*reinterpret_cast<uint32_t*>(&b01), *reinterpret_cast<uint32_t*>(&b23));
    reinterpret_cast<uint2*>(g_img_bf)[i] = av;
    reinterpret_cast<uint2*>(g_txt_bf)[i] = bv;
}

// ---------------- hashing ----------------------------------------------------
__device__ __forceinline__ unsigned long long splitmix64(unsigned long long x) {
    x += 0x9E3779B97F4A7C15ULL;
    x = (x ^ (x >> 30)) * 0xBF58476D1CE4E5B9ULL;
    x = (x ^ (x >> 27)) * 0x94D049BB133111EBULL;
    return x ^ (x >> 31);
}

__global__ void hash_kernel(const float* __restrict__ img) {
    const int j   = blockIdx.x;
    const int tid = threadIdx.x;
    const float* row = img + (size_t)j * D;
    unsigned long long h = 0ULL;
    for (int k = tid; k < D; k += blockDim.x) {
        unsigned int bits = __float_as_uint(row[k]);
        h += splitmix64(((unsigned long long)k << 32) ^ (unsigned long long)bits);
    }
    __shared__ unsigned long long sh[256];
    sh[tid] = h;
    __syncthreads();
    for (int s = 128; s > 0; s >>= 1) {
        if (tid < s) sh[tid] += sh[tid + s];
        __syncthreads();
    }
    if (tid == 0) g_hash[j] = sh[0];
}

__global__ void label_kernel(const float* __restrict__ img) {
    const int j   = blockIdx.x;
    const int tid = threadIdx.x;
    __shared__ int s_min;
    if (tid == 0) s_min = j;
    __syncthreads();
    const unsigned long long hj = g_hash[j];
    const float* rj = img + (size_t)j * D;
    for (int i = tid; i < j; i += blockDim.x) {
        if (g_hash[i] == hj) {
            const float* ri = img + (size_t)i * D;
            bool eq = true;
            for (int k = 0; k < D; k += 4) {
                float4 a = *reinterpret_cast<const float4*>(ri + k);
                float4 b = *reinterpret_cast<const float4*>(rj + k);
                if (a.x != b.x || a.y != b.y || a.z != b.z || a.w != b.w) { eq = false; break; }
            }
            if (eq) atomicMin(&s_min, i);
        }
    }
    __syncthreads();
    if (tid == 0) g_labels[j] = s_min;
}

// ---------------- mma.sync bf16 GEMM -----------------------------------------
// logits = scale * img @ txt^T (NT, both K-contiguous).
// CTA tile 64x64, 4 warps (2x2), warp tile 32x32. BK=32, cp.async double buffer.
#define BM 64
#define BN 64
#define BK 32
#define ROW_BYTES 80                    // 64 data bytes + 16 pad (bank-conflict-free)
#define TILE_SM   (64 * ROW_BYTES)      // 5120 B per operand tile
#define NSTAGE    (D / BK)              // 24

__global__ __launch_bounds__(128)
void gemm_mma_kernel(const float* __restrict__ scale_p) {
    __shared__ __align__(16) char sm[2 * 2 * TILE_SM];   // [stage][A/B] = 20480 B

    const int tid  = threadIdx.x;
    const int wid  = tid >> 5;
    const int lane = tid & 31;
    const int g    = lane >> 2;     // 0..7
    const int t    = lane & 3;      // 0..3
    const int mBase = blockIdx.y * BM;
    const int nBase = blockIdx.x * BN;
    const int wm = (wid >> 1) * 32;  // warp row offset in tile
    const int wn = (wid & 1) * 32;   // warp col offset in tile

    const uint32_t smem_base = smem_to_u32(sm);

    // loader: 512 x 16B chunks per stage (A tile 256 + B tile 256), 4 per thread
    const char* imgB = (const char*)g_img_bf;
    const char* txtB = (const char*)g_txt_bf;

    auto load_stage = [&](int s, int kt) {
        #pragma unroll
        for (int i = 0; i < 4; i++) {
            const int c   = tid + i * 128;     // 0..511
            const int ab  = c >> 8;            // 0 -> A(img), 1 -> B(txt)
            const int l   = c & 255;
            const int row = l >> 2;
            const int seg = (l & 3) * 16;      // byte offset in 64B row
            const char* gp = (ab ? txtB + ((size_t)(nBase + row) * D + kt) * 2
                                 : imgB + ((size_t)(mBase + row) * D + kt) * 2) + seg;
            uint32_t sp = smem_base + s * (2 * TILE_SM) + ab * TILE_SM + row * ROW_BYTES + seg;
            CP_ASYNC16(sp, gp);
        }
        CP_COMMIT();
    };

    float acc[2][4][4];
    #pragma unroll
    for (int mi = 0; mi < 2; mi++)
        #pragma unroll
        for (int ni = 0; ni < 4; ni++)
            #pragma unroll
            for (int q = 0; q < 4; q++) acc[mi][ni][q] = 0.0f;

    load_stage(0, 0);

    for (int ks = 0; ks < NSTAGE; ks++) {
        const int buf = ks & 1;
        if (ks + 1 < NSTAGE) {
            load_stage(buf ^ 1, (ks + 1) * BK);
            CP_WAIT(1);
        } else {
            CP_WAIT(0);
        }
        __syncthreads();

        const uint32_t aBase = smem_base + buf * (2 * TILE_SM);
        const uint32_t bBase = aBase + TILE_SM;

        #pragma unroll
        for (int h = 0; h < 2; h++) {          // two K16 halves of BK=32
            const int kb = h * 32;             // byte offset of K16 within row
            uint32_t a[2][4];
            #pragma unroll
            for (int mi = 0; mi < 2; mi++) {
                const uint32_t r0 = aBase + (wm + mi * 16 + g) * ROW_BYTES + kb;
                const uint32_t r8 = aBase + (wm + mi * 16 + g + 8) * ROW_BYTES + kb;
                a[mi][0] = lds32(r0 + t * 4);
                a[mi][1] = lds32(r8 + t * 4);
                a[mi][2] = lds32(r0 + t * 4 + 16);
                a[mi][3] = lds32(r8 + t * 4 + 16);
            }
            #pragma unroll
            for (int ni = 0; ni < 4; ni++) {
                uint32_t bfr[2];
                const uint32_t nb = bBase + (wn + ni * 8 + g) * ROW_BYTES + kb;
                bfr[0] = lds32(nb + t * 4);
                bfr[1] = lds32(nb + t * 4 + 16);
                mma16816(acc[0][ni], a[0], bfr);
                mma16816(acc[1][ni], a[1], bfr);
            }
        }
        __syncthreads();
    }

    // epilogue: scale + store
    const float s = *scale_p;
    #pragma unroll
    for (int mi = 0; mi < 2; mi++) {
        const int r0 = mBase + wm + mi * 16 + g;
        #pragma unroll
        for (int ni = 0; ni < 4; ni++) {
            const int col = nBase + wn + ni * 8 + t * 2;
            float2 lo = make_float2(acc[mi][ni][0] * s, acc[mi][ni][1] * s);
            float2 hi = make_float2(acc[mi][ni][2] * s, acc[mi][ni][3] * s);
            *reinterpret_cast<float2*>(g_logits + (size_t)r0 * B + col)       = lo;
            *reinterpret_cast<float2*>(g_logits + (size_t)(r0 + 8) * B + col) = hi;
        }
    }
}

// ---------------- per-row log-softmax loss ------------------------------------
__global__ void lse_kernel() {
    const int j   = blockIdx.x;
    const int tid = threadIdx.x;   // 256 threads, 4 elems each
    const float* row = g_logits + (size_t)j * B;

    float4 v = *reinterpret_cast<const float4*>(row + tid * 4);
    float lmax = fmaxf(fmaxf(v.x, v.y), fmaxf(v.z, v.w));

    __shared__ float sh[256];
    sh[tid] = lmax;
    __syncthreads();
    for (int s = 128; s > 0; s >>= 1) {
        if (tid < s) sh[tid] = fmaxf(sh[tid], sh[tid + s]);
        __syncthreads();
    }
    const float gmax = sh[0];
    __syncthreads();

    float lsum = expf(v.x - gmax) + expf(v.y - gmax) + expf(v.z - gmax) + expf(v.w - gmax);
    sh[tid] = lsum;
    __syncthreads();
    for (int s = 128; s > 0; s >>= 1) {
        if (tid < s) sh[tid] += sh[tid + s];
        __syncthreads();
    }
    if (tid == 0) {
        float lse = gmax + logf(sh[0]);
        g_loss[j] = lse - row[g_labels[j]];
    }
}

// ---------------- final deterministic mean -------------------------------------
__global__ void reduce_kernel(float* __restrict__ out) {
    const int tid = threadIdx.x;  // 256 threads
    float s = 0.0f;
    #pragma unroll
    for (int r = 0; r < 4; r++) s += g_loss[tid + r * 256];
    __shared__ float sh[256];
    sh[tid] = s;
    __syncthreads();
    for (int w = 128; w > 0; w >>= 1) {
        if (tid < w) sh[tid] += sh[tid + w];
        __syncthreads();
    }
    if (tid == 0) out[0] = sh[0] * (1.0f / (float)B);
}

// ---------------- entry ---------------------------------------------------------
extern "C" void kernel_launch(void* const* d_in, const int* in_sizes, int n_in,
                              void* d_out, int out_size) {
    const float* img   = (const float*)d_in[0];
    const float* txt   = (const float*)d_in[1];
    const float* scale = (const float*)d_in[2];
    float* out = (float*)d_out;

    convert_kernel<<<(B * D) / 4 / 256, 256>>>(img, txt);
    hash_kernel<<<B, 256>>>(img);
    label_kernel<<<B, 256>>>(img);
    dim3 grid(B / BN, B / BM);
    gemm_mma_kernel<<<grid, 128>>>(scale);
    lse_kernel<<<B, 256>>>();
    reduce_kernel<<<1, 256>>>(out);
}

// round 4
// speedup vs baseline: 3.5581x; 1.8498x over previous
#include <cuda_runtime.h>
#include <cuda_bf16.h>
#include <stdint.h>

#define B 1024
#define D 768

// ---------------- scratch (device globals; no allocation allowed) ----------
__device__ float              g_logits[B * B];   // 4 MB
__device__ __nv_bfloat16      g_img_bf[B * D];
__device__ __nv_bfloat16      g_txt_bf[B * D];
__device__ unsigned long long g_hash[B];
__device__ float              g_loss[B];

// ---------------- small asm helpers (all base-arch features) ----------------
__device__ __forceinline__ uint32_t smem_to_u32(const void* smem_ptr) {
    uint32_t addr;
    asm("{ .reg .u64 tmp; cvta.to.shared.u64 tmp, %1; cvt.u32.u64 %0, tmp; }"
        : "=r"(addr) : "l"(smem_ptr));
    return addr;
}
#define CP_ASYNC16(smem_u32, gptr) \
    asm volatile("cp.async.cg.shared.global [%0], [%1], 16;" \
                 :: "r"(smem_u32), "l"(gptr) : "memory")
#define CP_COMMIT() asm volatile("cp.async.commit_group;" ::: "memory")
#define CP_WAIT(N)  asm volatile("cp.async.wait_group %0;" :: "n"(N) : "memory")

#define LDSM_X4(R0, R1, R2, R3, ADDR) \
    asm volatile("ldmatrix.sync.aligned.m8n8.x4.shared.b16 {%0,%1,%2,%3}, [%4];" \
                 : "=r"(R0), "=r"(R1), "=r"(R2), "=r"(R3) : "r"(ADDR))

// mma.sync m16n8k16 row.col bf16 -> f32 accumulate (sm_80 baseline feature)
__device__ __forceinline__ void mma16816(float* d, const uint32_t* a, const uint32_t* b) {
    asm volatile(
        "mma.sync.aligned.m16n8k16.row.col.f32.bf16.bf16.f32 "
        "{%0,%1,%2,%3}, {%4,%5,%6,%7}, {%8,%9}, {%0,%1,%2,%3};"
        : "+f"(d[0]), "+f"(d[1]), "+f"(d[2]), "+f"(d[3])
        : "r"(a[0]), "r"(a[1]), "r"(a[2]), "r"(a[3]), "r"(b[0]), "r"(b[1]));
}

// ---------------- hashing ----------------------------------------------------
__device__ __forceinline__ unsigned long long splitmix64(unsigned long long x) {
    x += 0x9E3779B97F4A7C15ULL;
    x = (x ^ (x >> 30)) * 0xBF58476D1CE4E5B9ULL;
    x = (x ^ (x >> 27)) * 0x94D049BB133111EBULL;
    return x ^ (x >> 31);
}
__device__ __forceinline__ unsigned long long hmix(int k, float v) {
    return splitmix64(((unsigned long long)k << 32) ^ (unsigned long long)__float_as_uint(v));
}

// ---------------- fused fp32->bf16 convert + per-row hash --------------------
// One block per image row j. Threads 0..191 each handle one float4 of the img
// row (convert + hash) and one float4 of the txt row (convert).
__global__ __launch_bounds__(256)
void convert_hash_kernel(const float* __restrict__ img, const float* __restrict__ txt) {
    const int j   = blockIdx.x;
    const int tid = threadIdx.x;
    const int wid = tid >> 5;
    const int lane = tid & 31;

    unsigned long long h = 0ULL;
    if (tid < 192) {
        float4 a = reinterpret_cast<const float4*>(img + (size_t)j * D)[tid];
        float4 b = reinterpret_cast<const float4*>(txt + (size_t)j * D)[tid];
        __nv_bfloat162 a01 = __float22bfloat162_rn(make_float2(a.x, a.y));
        __nv_bfloat162 a23 = __float22bfloat162_rn(make_float2(a.z, a.w));
        __nv_bfloat162 b01 = __float22bfloat162_rn(make_float2(b.x, b.y));
        __nv_bfloat162 b23 = __float22bfloat162_rn(make_float2(b.z, b.w));
        reinterpret_cast<uint2*>(g_img_bf)[j * 192 + tid] =
            make_uint2(*reinterpret_cast<uint32_t*>(&a01), *reinterpret_cast<uint32_t*>(&a23));
        reinterpret_cast<uint2*>(g_txt_bf)[j * 192 + tid] =
            make_uint2(*reinterpret_cast<uint32_t*>(&b01), *reinterpret_cast<uint32_t*>(&b23));
        const int k = tid * 4;
        h = hmix(k, a.x) + hmix(k + 1, a.y) + hmix(k + 2, a.z) + hmix(k + 3, a.w);
    }
    // warp reduce, then cross-warp
    #pragma unroll
    for (int off = 16; off > 0; off >>= 1) h += __shfl_down_sync(0xffffffffu, h, off);
    __shared__ unsigned long long sw[8];
    if (lane == 0) sw[wid] = h;
    __syncthreads();
    if (tid == 0) {
        unsigned long long s = 0;
        #pragma unroll
        for (int w = 0; w < 8; w++) s += sw[w];
        g_hash[j] = s;
    }
}

// ---------------- mma.sync bf16 GEMM -----------------------------------------
// logits = scale * img @ txt^T. CTA 64x64, 4 warps (2x2), warp 32x32.
// BK=32, 3-stage cp.async pipeline, ldmatrix.x4 operand loads.
#define BM 64
#define BN 64
#define BK 32
#define ROW_BYTES 80                    // 64 data bytes + 16 pad (ldmatrix conflict-free)
#define TILE_SM   (64 * ROW_BYTES)      // 5120 B per operand tile
#define NKSTEP    (D / BK)              // 24
#define NPIPE     3

__global__ __launch_bounds__(128)
void gemm_mma_kernel(const float* __restrict__ scale_p) {
    __shared__ __align__(16) char sm[NPIPE * 2 * TILE_SM];   // 30720 B

    const int tid  = threadIdx.x;
    const int wid  = tid >> 5;
    const int lane = tid & 31;
    const int g    = lane >> 2;
    const int t    = lane & 3;
    const int mBase = blockIdx.y * BM;
    const int nBase = blockIdx.x * BN;
    const int wm = (wid >> 1) * 32;
    const int wn = (wid & 1) * 32;

    const uint32_t smem_base = smem_to_u32(sm);
    const char* imgB = (const char*)g_img_bf;
    const char* txtB = (const char*)g_txt_bf;

    auto load_stage = [&](int s, int kt) {
        #pragma unroll
        for (int i = 0; i < 4; i++) {
            const int c   = tid + i * 128;     // 0..511
            const int ab  = c >> 8;            // 0 -> A(img), 1 -> B(txt)
            const int l   = c & 255;
            const int row = l >> 2;
            const int seg = (l & 3) * 16;
            const char* gp = (ab ? txtB + ((size_t)(nBase + row) * D + kt) * 2
                                 : imgB + ((size_t)(mBase + row) * D + kt) * 2) + seg;
            uint32_t sp = smem_base + s * (2 * TILE_SM) + ab * TILE_SM + row * ROW_BYTES + seg;
            CP_ASYNC16(sp, gp);
        }
        CP_COMMIT();
    };

    // ldmatrix lane-derived addressing
    const int aRow   = lane & 15;
    const int aChunk = (lane >> 4) * 16;
    const int bRow   = ((lane >> 4) & 1) * 8 + (lane & 7);
    const int bChunk = ((lane >> 3) & 1) * 16;

    float acc[2][4][4];
    #pragma unroll
    for (int mi = 0; mi < 2; mi++)
        #pragma unroll
        for (int ni = 0; ni < 4; ni++)
            #pragma unroll
            for (int q = 0; q < 4; q++) acc[mi][ni][q] = 0.0f;

    load_stage(0, 0);
    load_stage(1, BK);

    for (int ks = 0; ks < NKSTEP; ks++) {
        const int buf = ks % NPIPE;
        if (ks + 2 < NKSTEP) { load_stage((ks + 2) % NPIPE, (ks + 2) * BK); CP_WAIT(2); }
        else if (ks + 1 < NKSTEP) { CP_WAIT(1); }
        else { CP_WAIT(0); }
        __syncthreads();

        const uint32_t aBase = smem_base + buf * (2 * TILE_SM);
        const uint32_t bBase = aBase + TILE_SM;

        #pragma unroll
        for (int h = 0; h < 2; h++) {
            const int kb = h * 32;
            uint32_t a[2][4], b[4][2];
            LDSM_X4(a[0][0], a[0][1], a[0][2], a[0][3],
                    aBase + (wm + 0 + aRow) * ROW_BYTES + kb + aChunk);
            LDSM_X4(a[1][0], a[1][1], a[1][2], a[1][3],
                    aBase + (wm + 16 + aRow) * ROW_BYTES + kb + aChunk);
            LDSM_X4(b[0][0], b[0][1], b[1][0], b[1][1],
                    bBase + (wn + 0 + bRow) * ROW_BYTES + kb + bChunk);
            LDSM_X4(b[2][0], b[2][1], b[3][0], b[3][1],
                    bBase + (wn + 16 + bRow) * ROW_BYTES + kb + bChunk);
            #pragma unroll
            for (int mi = 0; mi < 2; mi++)
                #pragma unroll
                for (int ni = 0; ni < 4; ni++)
                    mma16816(acc[mi][ni], a[mi], b[ni]);
        }
        __syncthreads();
    }

    // epilogue: scale + store
    const float s = *scale_p;
    #pragma unroll
    for (int mi = 0; mi < 2; mi++) {
        const int r0 = mBase + wm + mi * 16 + g;
        #pragma unroll
        for (int ni = 0; ni < 4; ni++) {
            const int col = nBase + wn + ni * 8 + t * 2;
            float2 lo = make_float2(acc[mi][ni][0] * s, acc[mi][ni][1] * s);
            float2 hi = make_float2(acc[mi][ni][2] * s, acc[mi][ni][3] * s);
            *reinterpret_cast<float2*>(g_logits + (size_t)r0 * B + col)       = lo;
            *reinterpret_cast<float2*>(g_logits + (size_t)(r0 + 8) * B + col) = hi;
        }
    }
}

// ---------------- fast exp (FMA pipe, not MUFU) -------------------------------
// e^x for x <= 0; 2^f minimax poly, exponent via bit assembly. rel err < 1e-6.
__device__ __forceinline__ float fexp(float x) {
    float y = fmaxf(x * 1.44269504088896340736f, -126.0f);
    float yi = floorf(y);
    float f = y - yi;
    float p = 1.8775767e-3f;
    p = fmaf(p, f, 8.9893397e-3f);
    p = fmaf(p, f, 5.5826318e-2f);
    p = fmaf(p, f, 2.4015361e-1f);
    p = fmaf(p, f, 6.9315308e-1f);
    p = fmaf(p, f, 1.0f);
    float sc = __int_as_float(((int)yi + 127) << 23);
    return p * sc;
}

// ---------------- per-row label + log-softmax loss (warp per row) -------------
__global__ __launch_bounds__(256)
void lse_kernel(const float* __restrict__ img) {
    const int wid  = threadIdx.x >> 5;
    const int lane = threadIdx.x & 31;
    const int j    = blockIdx.x * 8 + wid;
    const float* row = g_logits + (size_t)j * B;

    float4 v[8];
    float m = -3.4e38f;
    #pragma unroll
    for (int w = 0; w < 8; w++) {
        v[w] = reinterpret_cast<const float4*>(row)[lane + w * 32];
        m = fmaxf(m, fmaxf(fmaxf(v[w].x, v[w].y), fmaxf(v[w].z, v[w].w)));
    }
    #pragma unroll
    for (int off = 16; off > 0; off >>= 1) m = fmaxf(m, __shfl_xor_sync(0xffffffffu, m, off));

    float s = 0.0f;
    #pragma unroll
    for (int w = 0; w < 8; w++) {
        s += fexp(v[w].x - m) + fexp(v[w].y - m) + fexp(v[w].z - m) + fexp(v[w].w - m);
    }
    #pragma unroll
    for (int off = 16; off > 0; off >>= 1) s += __shfl_xor_sync(0xffffffffu, s, off);

    // label: first i < j with identical row (hash prefilter + exact verify)
    const unsigned long long hj = g_hash[j];
    int label = j;
    for (int base = 0; base < j && label == j; base += 32) {
        const int i = base + lane;
        const bool hit = (i < j) && (g_hash[i] == hj);
        unsigned mask = __ballot_sync(0xffffffffu, hit);
        while (mask && label == j) {
            const int ci = base + (__ffs(mask) - 1);
            bool eq = true;
            #pragma unroll
            for (int q = 0; q < 6; q++) {
                const int k4 = lane + q * 32;
                float4 a  = reinterpret_cast<const float4*>(img + (size_t)ci * D)[k4];
                float4 bb = reinterpret_cast<const float4*>(img + (size_t)j  * D)[k4];
                bool e = (a.x == bb.x) && (a.y == bb.y) && (a.z == bb.z) && (a.w == bb.w);
                if (!__all_sync(0xffffffffu, e)) { eq = false; break; }
            }
            if (eq) label = ci;
            mask &= mask - 1;
        }
    }

    if (lane == 0) {
        g_loss[j] = m + logf(s) - row[label];
    }
}

// ---------------- final deterministic mean -------------------------------------
__global__ void reduce_kernel(float* __restrict__ out) {
    const int tid = threadIdx.x;  // 256 threads
    float s = 0.0f;
    #pragma unroll
    for (int r = 0; r < 4; r++) s += g_loss[tid + r * 256];
    __shared__ float sh[256];
    sh[tid] = s;
    __syncthreads();
    for (int w = 128; w > 0; w >>= 1) {
        if (tid < w) sh[tid] += sh[tid + w];
        __syncthreads();
    }
    if (tid == 0) out[0] = sh[0] * (1.0f / (float)B);
}

// ---------------- entry ---------------------------------------------------------
extern "C" void kernel_launch(void* const* d_in, const int* in_sizes, int n_in,
                              void* d_out, int out_size) {
    const float* img   = (const float*)d_in[0];
    const float* txt   = (const float*)d_in[1];
    const float* scale = (const float*)d_in[2];
    float* out = (float*)d_out;

    convert_hash_kernel<<<B, 256>>>(img, txt);
    dim3 grid(B / BN, B / BM);
    gemm_mma_kernel<<<grid, 128>>>(scale);
    lse_kernel<<<B / 8, 256>>>(img);
    reduce_kernel<<<1, 256>>>(out);
}